// round 4
// baseline (speedup 1.0000x reference)
#include <cuda_runtime.h>

typedef unsigned long long ull;

// B=4096 rows -> 2048 row-pairs (f32x2-packed), T=256, F=64, 4H=64, D=64.
// Phase 1: z[t][pair][colslot] = x_t @ W + b   (pre-permuted for phase 2)
// Phase 2: recurrent scan, lane j owns cols {j, j+8, ..., j+56} => gate-local.

#define NP 2048
#define TT 256
#define ZSTRIDE ((size_t)NP * 64)

__device__ double g_z[(size_t)TT * NP * 64];   // 256 MB scratch

__device__ __forceinline__ ull fma2(ull a, ull b, ull c) {
    ull d;
    asm("fma.rn.f32x2 %0, %1, %2, %3;" : "=l"(d) : "l"(a), "l"(b), "l"(c));
    return d;
}
__device__ __forceinline__ ull d2u(double d){ return (ull)__double_as_longlong(d); }
__device__ __forceinline__ double u2d(ull u){ return __longlong_as_double((long long)u); }
__device__ __forceinline__ double dupf(float v){
    unsigned u = __float_as_uint(v);
    return u2d(((ull)u << 32) | u);
}
__device__ __forceinline__ float lof(ull u){ return __uint_as_float((unsigned)u); }
__device__ __forceinline__ float hif(ull u){ return __uint_as_float((unsigned)(u >> 32)); }
__device__ __forceinline__ float tanha(float x){
    float y; asm("tanh.approx.f32 %0, %1;" : "=f"(y) : "f"(x)); return y;
}
__device__ __forceinline__ float sigf(float z){ return fmaf(0.5f, tanha(0.5f * z), 0.5f); }
// col c -> shared slot: lane j = c&7 owns it at position (c>>3)
__device__ __forceinline__ int soff2(int c){ return ((c & 7) << 3) | (c >> 3); }

// ---------------- Phase 1: xw = x_t @ W + b ----------------
// grid (32, 256): blockIdx.x = 128-row block, blockIdx.y = t. 128 threads.
// Warp w: pairs [16w,16w+16); lane (lp,j): 4 pairs 16w+4lp+q, 8 cols {j+8m}.
__global__ void __launch_bounds__(128, 3) p1_kernel(
    const float* __restrict__ x, const float* __restrict__ W,
    const float* __restrict__ b)
{
    extern __shared__ double sm1[];
    double* wd = sm1;            // 64*64 dup'd W, swizzled
    double* xs = wd + 4096;      // 64 pairs * stride 65, {rowA,rowB} packed
    double* bd = xs + 64 * 65;   // 64 dup'd bias, swizzled

    const int tid = threadIdx.x;
    const int t = blockIdx.y;
    const int bb = blockIdx.x;

    for (int idx = tid; idx < 4096; idx += 128) {
        int f = idx >> 6, c = idx & 63;
        wd[f * 64 + soff2(c)] = dupf(W[idx]);
    }
    if (tid < 64) bd[soff2(tid)] = dupf(b[tid]);

    // stage this CTA's 128 x rows, pair-interleaved
    {
        const int r = tid;
        const float* xr = x + ((size_t)(bb * 128 + r) * 256 + t) * 64;
        float* xsF = (float*)xs;
        const int pr = r >> 1, sub = r & 1;
#pragma unroll
        for (int f4 = 0; f4 < 16; f4++) {
            float4 v = ((const float4*)xr)[f4];
            int base = (pr * 65 + f4 * 4) * 2 + sub;
            xsF[base + 0] = v.x; xsF[base + 2] = v.y;
            xsF[base + 4] = v.z; xsF[base + 6] = v.w;
        }
    }
    __syncthreads();

    const int warp = tid >> 5, lane = tid & 31;
    const int lp = lane >> 3, j = lane & 7;
    const int p0 = warp * 16 + lp * 4;

    ull acc[4][8];
    {
        const double2* bp = (const double2*)(bd + j * 8);
#pragma unroll
        for (int i = 0; i < 4; i++) {
            double2 v = bp[i];
#pragma unroll
            for (int q = 0; q < 4; q++) {
                acc[q][2 * i] = d2u(v.x);
                acc[q][2 * i + 1] = d2u(v.y);
            }
        }
    }
#pragma unroll 4
    for (int f = 0; f < 64; f++) {
        ull xv[4];
#pragma unroll
        for (int q = 0; q < 4; q++) xv[q] = d2u(xs[(p0 + q) * 65 + f]);
        const double2* wp = (const double2*)(wd + f * 64 + j * 8);
#pragma unroll
        for (int i = 0; i < 4; i++) {
            double2 wv = wp[i];
            ull wx = d2u(wv.x), wy = d2u(wv.y);
#pragma unroll
            for (int q = 0; q < 4; q++) {
                acc[q][2 * i]     = fma2(xv[q], wx, acc[q][2 * i]);
                acc[q][2 * i + 1] = fma2(xv[q], wy, acc[q][2 * i + 1]);
            }
        }
    }
#pragma unroll
    for (int q = 0; q < 4; q++) {
        size_t pairG = (size_t)bb * 64 + p0 + q;
        double2* dst = (double2*)(g_z + ((size_t)t * NP + pairG) * 64 + j * 8);
#pragma unroll
        for (int i = 0; i < 4; i++)
            dst[i] = make_double2(u2d(acc[q][2 * i]), u2d(acc[q][2 * i + 1]));
    }
}

// ---------------- Phase 2: recurrent scan + dense ----------------
// 512 CTAs x 32 threads. CTA w: pairs 4w..4w+4. lane (p,j):
// owns units j, j+8 of pair p; cols {j+8m} m=0..7 -> gates lane-local.
__global__ void __launch_bounds__(32, 8) p2_kernel(
    const float* __restrict__ U, const float* __restrict__ Wdn,
    const float* __restrict__ bdn, float* __restrict__ out)
{
    __shared__ double U2s[16 * 64];
    __shared__ double Wd2s[16 * 64];
    __shared__ double bdd[64];
    __shared__ double h2[4 * 18];

    const int lane = threadIdx.x;
    for (int idx = lane; idx < 1024; idx += 32) {
        int k = idx >> 6, c = idx & 63;
        U2s[k * 64 + soff2(c)]  = dupf(U[idx]);
        Wd2s[k * 64 + soff2(c)] = dupf(Wdn[idx]);
    }
    for (int idx = lane; idx < 64; idx += 32) bdd[soff2(idx)] = dupf(bdn[idx]);
    for (int idx = lane; idx < 72; idx += 32) h2[idx] = 0.0;
    __syncwarp();

    const int p = lane >> 3, j = lane & 7;
    const size_t P = (size_t)blockIdx.x * 4 + p;
    const double* zbase = g_z + P * 64 + j * 8;

    double2 zc[4], zn[4];
#pragma unroll
    for (int i = 0; i < 4; i++) zc[i] = ((const double2*)zbase)[i];

    float cA0 = 0.f, cB0 = 0.f, cA1 = 0.f, cB1 = 0.f;

#pragma unroll 1
    for (int t = 0; t < 256; t++) {
        const int tp = (t < 255) ? t + 1 : 255;
        const double2* znp = (const double2*)(zbase + (size_t)tp * ZSTRIDE);
#pragma unroll
        for (int i = 0; i < 4; i++) zn[i] = znp[i];

        ull acc[8];
#pragma unroll
        for (int i = 0; i < 4; i++) {
            acc[2 * i] = d2u(zc[i].x);
            acc[2 * i + 1] = d2u(zc[i].y);
        }
#pragma unroll
        for (int k = 0; k < 16; k++) {
            ull hv = d2u(h2[p * 18 + k]);
            const double2* up = (const double2*)(U2s + k * 64 + j * 8);
#pragma unroll
            for (int i = 0; i < 4; i++) {
                double2 uv = up[i];
                acc[2 * i]     = fma2(hv, d2u(uv.x), acc[2 * i]);
                acc[2 * i + 1] = fma2(hv, d2u(uv.y), acc[2 * i + 1]);
            }
        }
        // acc[m] = col j+8m. unit j: i=m0 f=m2 g=m4 o=m6; unit j+8: m1,m3,m5,m7
        float iA0 = sigf(lof(acc[0])), iB0 = sigf(hif(acc[0]));
        float iA1 = sigf(lof(acc[1])), iB1 = sigf(hif(acc[1]));
        float fA0 = sigf(lof(acc[2])), fB0 = sigf(hif(acc[2]));
        float fA1 = sigf(lof(acc[3])), fB1 = sigf(hif(acc[3]));
        float gA0 = fmaxf(lof(acc[4]), 0.f), gB0 = fmaxf(hif(acc[4]), 0.f);
        float gA1 = fmaxf(lof(acc[5]), 0.f), gB1 = fmaxf(hif(acc[5]), 0.f);
        float oA0 = sigf(lof(acc[6])), oB0 = sigf(hif(acc[6]));
        float oA1 = sigf(lof(acc[7])), oB1 = sigf(hif(acc[7]));

        cA0 = fA0 * cA0 + iA0 * gA0;  cB0 = fB0 * cB0 + iB0 * gB0;
        cA1 = fA1 * cA1 + iA1 * gA1;  cB1 = fB1 * cB1 + iB1 * gB1;

        float hA0 = oA0 * fmaxf(cA0, 0.f), hB0 = oB0 * fmaxf(cB0, 0.f);
        float hA1 = oA1 * fmaxf(cA1, 0.f), hB1 = oB1 * fmaxf(cB1, 0.f);

        __syncwarp();
        h2[p * 18 + j]     = __hiloint2double(__float_as_int(hB0), __float_as_int(hA0));
        h2[p * 18 + j + 8] = __hiloint2double(__float_as_int(hB1), __float_as_int(hA1));
        __syncwarp();

#pragma unroll
        for (int i = 0; i < 4; i++) zc[i] = zn[i];
    }

    // dense: out = normalize(sigmoid(h @ Wd + bd))
    ull acc[8];
    {
        const double2* bp = (const double2*)(bdd + j * 8);
#pragma unroll
        for (int i = 0; i < 4; i++) {
            double2 v = bp[i];
            acc[2 * i] = d2u(v.x);
            acc[2 * i + 1] = d2u(v.y);
        }
    }
#pragma unroll
    for (int k = 0; k < 16; k++) {
        ull hv = d2u(h2[p * 18 + k]);
        const double2* wp = (const double2*)(Wd2s + k * 64 + j * 8);
#pragma unroll
        for (int i = 0; i < 4; i++) {
            double2 wv = wp[i];
            acc[2 * i]     = fma2(hv, d2u(wv.x), acc[2 * i]);
            acc[2 * i + 1] = fma2(hv, d2u(wv.y), acc[2 * i + 1]);
        }
    }
    float sA[8], sB[8], sumA = 0.f, sumB = 0.f;
#pragma unroll
    for (int m = 0; m < 8; m++) {
        sA[m] = sigf(lof(acc[m]));  sB[m] = sigf(hif(acc[m]));
        sumA += sA[m];  sumB += sB[m];
    }
#pragma unroll
    for (int off = 1; off < 8; off <<= 1) {
        sumA += __shfl_xor_sync(0xffffffffu, sumA, off);
        sumB += __shfl_xor_sync(0xffffffffu, sumB, off);
    }
    const float invA = __fdividef(1.f, sumA);
    const float invB = __fdividef(1.f, sumB);
    float* oA = out + (size_t)(2 * P) * 64;
    float* oB = oA + 64;
#pragma unroll
    for (int m = 0; m < 8; m++) {
        oA[j + 8 * m] = sA[m] * invA;
        oB[j + 8 * m] = sB[m] * invB;
    }
}

extern "C" void kernel_launch(void* const* d_in, const int* in_sizes, int n_in,
                              void* d_out, int out_size)
{
    const float* x  = (const float*)d_in[0];
    const float* W  = (const float*)d_in[1];
    const float* U  = (const float*)d_in[2];
    const float* b  = (const float*)d_in[3];
    const float* Wd = (const float*)d_in[4];
    const float* bd = (const float*)d_in[5];
    float* out = (float*)d_out;

    const size_t sh1 = (4096 + 64 * 65 + 64) * sizeof(double);  // 66560 B
    cudaFuncSetAttribute(p1_kernel, cudaFuncAttributeMaxDynamicSharedMemorySize, (int)sh1);
    p1_kernel<<<dim3(32, 256), 128, sh1>>>(x, W, b);
    p2_kernel<<<512, 32>>>(U, Wd, bd, out);
}

// round 5
// speedup vs baseline: 1.0015x; 1.0015x over previous
#include <cuda_runtime.h>

typedef unsigned long long ull;

// B=4096 rows -> 2048 row-pairs (f32x2-packed), T=256, F=64, 4H=64, D=64.
// Phase 1: z[t][pair][colslot] = x_t @ W + b   (pre-permuted for phase 2)
// Phase 2: recurrent scan, lane j owns cols {j, j+8, ..., j+56} => gate-local.

#define NP 2048
#define TT 256
#define ZSTRIDE ((size_t)NP * 64)

__device__ double g_z[(size_t)TT * NP * 64];   // 256 MB scratch

__device__ __forceinline__ ull fma2(ull a, ull b, ull c) {
    ull d;
    asm("fma.rn.f32x2 %0, %1, %2, %3;" : "=l"(d) : "l"(a), "l"(b), "l"(c));
    return d;
}
__device__ __forceinline__ ull d2u(double d){ return (ull)__double_as_longlong(d); }
__device__ __forceinline__ double u2d(ull u){ return __longlong_as_double((long long)u); }
__device__ __forceinline__ double dupf(float v){
    unsigned u = __float_as_uint(v);
    return u2d(((ull)u << 32) | u);
}
__device__ __forceinline__ float lof(ull u){ return __uint_as_float((unsigned)u); }
__device__ __forceinline__ float hif(ull u){ return __uint_as_float((unsigned)(u >> 32)); }
__device__ __forceinline__ float tanha(float x){
    float y; asm("tanh.approx.f32 %0, %1;" : "=f"(y) : "f"(x)); return y;
}
__device__ __forceinline__ float sigf(float z){ return fmaf(0.5f, tanha(0.5f * z), 0.5f); }
// col c -> shared slot: lane j = c&7 owns it at position (c>>3)
__device__ __forceinline__ int soff2(int c){ return ((c & 7) << 3) | (c >> 3); }

// ---------------- Phase 1: xw = x_t @ W + b ----------------
// grid (32, 256): blockIdx.x = 128-row block, blockIdx.y = t. 128 threads.
// Warp w: pairs [16w,16w+16); lane (lp,j): 4 pairs 16w+4lp+q, 8 cols {j+8m}.
__global__ void __launch_bounds__(128, 3) p1_kernel(
    const float* __restrict__ x, const float* __restrict__ W,
    const float* __restrict__ b)
{
    extern __shared__ double sm1[];
    double* wd = sm1;            // 64*64 dup'd W, swizzled
    double* xs = wd + 4096;      // 64 pairs * stride 65, {rowA,rowB} packed
    double* bd = xs + 64 * 65;   // 64 dup'd bias, swizzled

    const int tid = threadIdx.x;
    const int t = blockIdx.y;
    const int bb = blockIdx.x;

    for (int idx = tid; idx < 4096; idx += 128) {
        int f = idx >> 6, c = idx & 63;
        wd[f * 64 + soff2(c)] = dupf(W[idx]);
    }
    if (tid < 64) bd[soff2(tid)] = dupf(b[tid]);

    // stage this CTA's 128 x rows, pair-interleaved
    {
        const int r = tid;
        const float* xr = x + ((size_t)(bb * 128 + r) * 256 + t) * 64;
        float* xsF = (float*)xs;
        const int pr = r >> 1, sub = r & 1;
#pragma unroll
        for (int f4 = 0; f4 < 16; f4++) {
            float4 v = ((const float4*)xr)[f4];
            int base = (pr * 65 + f4 * 4) * 2 + sub;
            xsF[base + 0] = v.x; xsF[base + 2] = v.y;
            xsF[base + 4] = v.z; xsF[base + 6] = v.w;
        }
    }
    __syncthreads();

    const int warp = tid >> 5, lane = tid & 31;
    const int lp = lane >> 3, j = lane & 7;
    const int p0 = warp * 16 + lp * 4;

    ull acc[4][8];
    {
        const double2* bp = (const double2*)(bd + j * 8);
#pragma unroll
        for (int i = 0; i < 4; i++) {
            double2 v = bp[i];
#pragma unroll
            for (int q = 0; q < 4; q++) {
                acc[q][2 * i] = d2u(v.x);
                acc[q][2 * i + 1] = d2u(v.y);
            }
        }
    }
#pragma unroll 4
    for (int f = 0; f < 64; f++) {
        ull xv[4];
#pragma unroll
        for (int q = 0; q < 4; q++) xv[q] = d2u(xs[(p0 + q) * 65 + f]);
        const double2* wp = (const double2*)(wd + f * 64 + j * 8);
#pragma unroll
        for (int i = 0; i < 4; i++) {
            double2 wv = wp[i];
            ull wx = d2u(wv.x), wy = d2u(wv.y);
#pragma unroll
            for (int q = 0; q < 4; q++) {
                acc[q][2 * i]     = fma2(xv[q], wx, acc[q][2 * i]);
                acc[q][2 * i + 1] = fma2(xv[q], wy, acc[q][2 * i + 1]);
            }
        }
    }
#pragma unroll
    for (int q = 0; q < 4; q++) {
        size_t pairG = (size_t)bb * 64 + p0 + q;
        double2* dst = (double2*)(g_z + ((size_t)t * NP + pairG) * 64 + j * 8);
#pragma unroll
        for (int i = 0; i < 4; i++)
            dst[i] = make_double2(u2d(acc[q][2 * i]), u2d(acc[q][2 * i + 1]));
    }
}

// ---------------- Phase 2: recurrent scan + dense ----------------
// 512 CTAs x 32 threads. CTA w: pairs 4w..4w+4. lane (p,j):
// owns units j, j+8 of pair p; cols {j+8m} m=0..7 -> gates lane-local.
__global__ void __launch_bounds__(32, 8) p2_kernel(
    const float* __restrict__ U, const float* __restrict__ Wdn,
    const float* __restrict__ bdn, float* __restrict__ out)
{
    __shared__ double U2s[16 * 64];
    __shared__ double Wd2s[16 * 64];
    __shared__ double bdd[64];
    __shared__ double h2[4 * 18];

    const int lane = threadIdx.x;
    for (int idx = lane; idx < 1024; idx += 32) {
        int k = idx >> 6, c = idx & 63;
        U2s[k * 64 + soff2(c)]  = dupf(U[idx]);
        Wd2s[k * 64 + soff2(c)] = dupf(Wdn[idx]);
    }
    for (int idx = lane; idx < 64; idx += 32) bdd[soff2(idx)] = dupf(bdn[idx]);
    for (int idx = lane; idx < 72; idx += 32) h2[idx] = 0.0;
    __syncwarp();

    const int p = lane >> 3, j = lane & 7;
    const size_t P = (size_t)blockIdx.x * 4 + p;
    const double* zbase = g_z + P * 64 + j * 8;

    double2 zc[4], zn[4];
#pragma unroll
    for (int i = 0; i < 4; i++) zc[i] = ((const double2*)zbase)[i];

    float cA0 = 0.f, cB0 = 0.f, cA1 = 0.f, cB1 = 0.f;

#pragma unroll 1
    for (int t = 0; t < 256; t++) {
        const int tp = (t < 255) ? t + 1 : 255;
        const double2* znp = (const double2*)(zbase + (size_t)tp * ZSTRIDE);
#pragma unroll
        for (int i = 0; i < 4; i++) zn[i] = znp[i];

        ull acc[8];
#pragma unroll
        for (int i = 0; i < 4; i++) {
            acc[2 * i] = d2u(zc[i].x);
            acc[2 * i + 1] = d2u(zc[i].y);
        }
#pragma unroll
        for (int k = 0; k < 16; k++) {
            ull hv = d2u(h2[p * 18 + k]);
            const double2* up = (const double2*)(U2s + k * 64 + j * 8);
#pragma unroll
            for (int i = 0; i < 4; i++) {
                double2 uv = up[i];
                acc[2 * i]     = fma2(hv, d2u(uv.x), acc[2 * i]);
                acc[2 * i + 1] = fma2(hv, d2u(uv.y), acc[2 * i + 1]);
            }
        }
        // acc[m] = col j+8m. unit j: i=m0 f=m2 g=m4 o=m6; unit j+8: m1,m3,m5,m7
        float iA0 = sigf(lof(acc[0])), iB0 = sigf(hif(acc[0]));
        float iA1 = sigf(lof(acc[1])), iB1 = sigf(hif(acc[1]));
        float fA0 = sigf(lof(acc[2])), fB0 = sigf(hif(acc[2]));
        float fA1 = sigf(lof(acc[3])), fB1 = sigf(hif(acc[3]));
        float gA0 = fmaxf(lof(acc[4]), 0.f), gB0 = fmaxf(hif(acc[4]), 0.f);
        float gA1 = fmaxf(lof(acc[5]), 0.f), gB1 = fmaxf(hif(acc[5]), 0.f);
        float oA0 = sigf(lof(acc[6])), oB0 = sigf(hif(acc[6]));
        float oA1 = sigf(lof(acc[7])), oB1 = sigf(hif(acc[7]));

        cA0 = fA0 * cA0 + iA0 * gA0;  cB0 = fB0 * cB0 + iB0 * gB0;
        cA1 = fA1 * cA1 + iA1 * gA1;  cB1 = fB1 * cB1 + iB1 * gB1;

        float hA0 = oA0 * fmaxf(cA0, 0.f), hB0 = oB0 * fmaxf(cB0, 0.f);
        float hA1 = oA1 * fmaxf(cA1, 0.f), hB1 = oB1 * fmaxf(cB1, 0.f);

        __syncwarp();
        h2[p * 18 + j]     = __hiloint2double(__float_as_int(hB0), __float_as_int(hA0));
        h2[p * 18 + j + 8] = __hiloint2double(__float_as_int(hB1), __float_as_int(hA1));
        __syncwarp();

#pragma unroll
        for (int i = 0; i < 4; i++) zc[i] = zn[i];
    }

    // dense: out = normalize(sigmoid(h @ Wd + bd))
    ull acc[8];
    {
        const double2* bp = (const double2*)(bdd + j * 8);
#pragma unroll
        for (int i = 0; i < 4; i++) {
            double2 v = bp[i];
            acc[2 * i] = d2u(v.x);
            acc[2 * i + 1] = d2u(v.y);
        }
    }
#pragma unroll
    for (int k = 0; k < 16; k++) {
        ull hv = d2u(h2[p * 18 + k]);
        const double2* wp = (const double2*)(Wd2s + k * 64 + j * 8);
#pragma unroll
        for (int i = 0; i < 4; i++) {
            double2 wv = wp[i];
            acc[2 * i]     = fma2(hv, d2u(wv.x), acc[2 * i]);
            acc[2 * i + 1] = fma2(hv, d2u(wv.y), acc[2 * i + 1]);
        }
    }
    float sA[8], sB[8], sumA = 0.f, sumB = 0.f;
#pragma unroll
    for (int m = 0; m < 8; m++) {
        sA[m] = sigf(lof(acc[m]));  sB[m] = sigf(hif(acc[m]));
        sumA += sA[m];  sumB += sB[m];
    }
#pragma unroll
    for (int off = 1; off < 8; off <<= 1) {
        sumA += __shfl_xor_sync(0xffffffffu, sumA, off);
        sumB += __shfl_xor_sync(0xffffffffu, sumB, off);
    }
    const float invA = __fdividef(1.f, sumA);
    const float invB = __fdividef(1.f, sumB);
    float* oA = out + (size_t)(2 * P) * 64;
    float* oB = oA + 64;
#pragma unroll
    for (int m = 0; m < 8; m++) {
        oA[j + 8 * m] = sA[m] * invA;
        oB[j + 8 * m] = sB[m] * invB;
    }
}

extern "C" void kernel_launch(void* const* d_in, const int* in_sizes, int n_in,
                              void* d_out, int out_size)
{
    const float* x  = (const float*)d_in[0];
    const float* W  = (const float*)d_in[1];
    const float* U  = (const float*)d_in[2];
    const float* b  = (const float*)d_in[3];
    const float* Wd = (const float*)d_in[4];
    const float* bd = (const float*)d_in[5];
    float* out = (float*)d_out;

    const size_t sh1 = (4096 + 64 * 65 + 64) * sizeof(double);  // 66560 B
    cudaFuncSetAttribute(p1_kernel, cudaFuncAttributeMaxDynamicSharedMemorySize, (int)sh1);
    p1_kernel<<<dim3(32, 256), 128, sh1>>>(x, W, b);
    p2_kernel<<<512, 32>>>(U, Wd, bd, out);
}

// round 7
// speedup vs baseline: 2.6031x; 2.5991x over previous
#include <cuda_runtime.h>

typedef unsigned long long ull;

// B=4096, T=256, F=64, 4H=64, D=64.
// g_zf[t][row][c] (floats, natural layout): z = x_t @ W + b.
#define NB 4096
#define ZT ((size_t)NB * 64)

__device__ float g_zf[(size_t)256 * NB * 64];   // 256 MB scratch

__device__ __forceinline__ ull fma2(ull a, ull b, ull c) {
    ull d;
    asm("fma.rn.f32x2 %0, %1, %2, %3;" : "=l"(d) : "l"(a), "l"(b), "l"(c));
    return d;
}
__device__ __forceinline__ ull d2u(double d){ return (ull)__double_as_longlong(d); }
__device__ __forceinline__ double u2d(ull u){ return __longlong_as_double((long long)u); }
__device__ __forceinline__ ull pack2(float lo, float hi){
    return ((ull)__float_as_uint(hi) << 32) | (ull)__float_as_uint(lo);
}
__device__ __forceinline__ double dupd(float v){
    int i = __float_as_int(v); return __hiloint2double(i, i);
}
__device__ __forceinline__ float lof(ull u){ return __uint_as_float((unsigned)u); }
__device__ __forceinline__ float hif(ull u){ return __uint_as_float((unsigned)(u >> 32)); }
__device__ __forceinline__ float tanha(float x){
    float y; asm("tanh.approx.f32 %0, %1;" : "=f"(y) : "f"(x)); return y;
}
__device__ __forceinline__ float sigf(float z){ return fmaf(0.5f, tanha(0.5f * z), 0.5f); }

// ---------------- Phase 1: z[t][row][:] = x[row][t][:] @ W + b ----------------
// Grid 4096 (1 row/CTA), 128 threads. Thread (tg=tid>>3, j=tid&7): cols [8j,8j+8)
// as 4 {c,c+1} f32x2 pairs; t = pass*64 + tg + 16s, s=0..3, 4 passes.
__global__ void __launch_bounds__(128, 4) p1_kernel(
    const float* __restrict__ x, const float* __restrict__ W,
    const float* __restrict__ b)
{
    extern __shared__ double sm[];
    double* Wp = sm;           // 64 f * 17 16B-slots = 2176 doubles (pair-packed W)
    double* xd = Wp + 2176;    // 64 t * 65 dup'd {x,x} doubles

    const int tid = threadIdx.x;
    const int row = blockIdx.x;

    // W[f][2P],W[f][2P+1] -> packed double at slot u = 2j+(j>>2)+(q>>1), half q&1
    for (int idx = tid; idx < 2048; idx += 128) {
        int f = idx >> 5, P = idx & 31;
        int j = P >> 2, q = P & 3;
        int u = 2 * j + (j >> 2) + (q >> 1);
        Wp[(f * 17 + u) * 2 + (q & 1)] =
            __hiloint2double(__float_as_int(W[f * 64 + 2 * P + 1]),
                             __float_as_int(W[f * 64 + 2 * P]));
    }

    const int j = tid & 7, tg = tid >> 3;
    ull bp[4];
#pragma unroll
    for (int q = 0; q < 4; q++)
        bp[q] = pack2(b[8 * j + 2 * q], b[8 * j + 2 * q + 1]);

    const double* wbase = Wp + (2 * j + (j >> 2)) * 2;

    for (int pass = 0; pass < 4; pass++) {
        __syncthreads();
        // stage x[row][pass*64 .. +64][:] = 16 KB contiguous, duplicated
        const float4* xsrc = (const float4*)(x + ((size_t)row * 256 + pass * 64) * 64);
#pragma unroll
        for (int it = 0; it < 8; it++) {
            int k = it * 128 + tid;
            float4 v = xsrc[k];
            double* d = xd + (k >> 4) * 65 + (k & 15) * 4;
            d[0] = dupd(v.x); d[1] = dupd(v.y);
            d[2] = dupd(v.z); d[3] = dupd(v.w);
        }
        __syncthreads();

        ull acc[4][4];
#pragma unroll
        for (int s = 0; s < 4; s++)
#pragma unroll
            for (int q = 0; q < 4; q++) acc[s][q] = bp[q];

        const double* xr = xd + tg * 65;     // t = tg + 16s -> +s*16*65
#pragma unroll 8
        for (int f = 0; f < 64; f++) {
            double2 w01 = *(const double2*)(wbase + f * 34);
            double2 w23 = *(const double2*)(wbase + f * 34 + 2);
            ull w0 = d2u(w01.x), w1 = d2u(w01.y);
            ull w2 = d2u(w23.x), w3 = d2u(w23.y);
#pragma unroll
            for (int s = 0; s < 4; s++) {
                ull xv = d2u(xr[s * 1040 + f]);
                acc[s][0] = fma2(xv, w0, acc[s][0]);
                acc[s][1] = fma2(xv, w1, acc[s][1]);
                acc[s][2] = fma2(xv, w2, acc[s][2]);
                acc[s][3] = fma2(xv, w3, acc[s][3]);
            }
        }
#pragma unroll
        for (int s = 0; s < 4; s++) {
            int t = pass * 64 + tg + 16 * s;
            double2* zo = (double2*)(g_zf + ((size_t)t * NB + row) * 64 + 8 * j);
            zo[0] = make_double2(u2d(acc[s][0]), u2d(acc[s][1]));
            zo[1] = make_double2(u2d(acc[s][2]), u2d(acc[s][3]));
        }
    }
}

// ---------------- Phase 2: recurrent scan + dense ----------------
// 256 CTAs x 128. Warp = 2 pairs (4 rows): p=lane>>4, jj=lane&15.
// Lane jj owns unit jj of pair p: cols jj+16m (m=i,f,g,o) -> gates lane-local.
__global__ void __launch_bounds__(128, 2) p2_kernel(
    const float* __restrict__ U, const float* __restrict__ Wdn,
    const float* __restrict__ bdn, float* __restrict__ out)
{
    __shared__ double U2d[16 * 64];    // dup'd {u,u}
    __shared__ double Wd2d[16 * 64];   // dup'd
    __shared__ double bdd[64];         // dup'd
    __shared__ double h2[4][2][16];    // packed {hA,hB} per unit

    const int tid = threadIdx.x;
    for (int idx = tid; idx < 1024; idx += 128) {
        U2d[idx]  = dupd(U[idx]);
        Wd2d[idx] = dupd(Wdn[idx]);
    }
    if (tid < 64) bdd[tid] = dupd(bdn[tid]);

    const int w = tid >> 5, lane = tid & 31;
    const int p = lane >> 4, jj = lane & 15;
    if (lane < 16) { h2[w][0][lane] = 0.0; h2[w][1][lane] = 0.0; }
    __syncthreads();

    const size_t P = (size_t)blockIdx.x * 8 + w * 2 + p;
    const float* zA = g_zf + (size_t)(2 * P) * 64 + jj;   // row 2P
    const float* zB = zA + 64;                            // row 2P+1

    float za[4][4], zb[4][4];
#pragma unroll
    for (int r = 0; r < 4; r++)
#pragma unroll
        for (int m = 0; m < 4; m++) {
            za[r][m] = zA[(size_t)r * ZT + 16 * m];
            zb[r][m] = zB[(size_t)r * ZT + 16 * m];
        }

    float cA = 0.f, cB = 0.f;
    const double* hrow = &h2[w][p][0];
    const double* ub = U2d + jj;

#pragma unroll 1
    for (int t0 = 0; t0 < 256; t0 += 4) {
#pragma unroll
        for (int s = 0; s < 4; s++) {
            ull acc[4];
#pragma unroll
            for (int m = 0; m < 4; m++) acc[m] = pack2(za[s][m], zb[s][m]);
#pragma unroll
            for (int k = 0; k < 16; k++) {
                ull hv = d2u(hrow[k]);
                const double* up = ub + k * 64;
                acc[0] = fma2(hv, d2u(up[0]),  acc[0]);
                acc[1] = fma2(hv, d2u(up[16]), acc[1]);
                acc[2] = fma2(hv, d2u(up[32]), acc[2]);
                acc[3] = fma2(hv, d2u(up[48]), acc[3]);
            }
            // prefetch z[t+4] into the slot just consumed
            {
                int tn = t0 + s + 4; if (tn > 255) tn = 255;
                size_t off = (size_t)tn * ZT;
#pragma unroll
                for (int m = 0; m < 4; m++) {
                    za[s][m] = zA[off + 16 * m];
                    zb[s][m] = zB[off + 16 * m];
                }
            }
            float iA = sigf(lof(acc[0])), iB = sigf(hif(acc[0]));
            float fA = sigf(lof(acc[1])), fB = sigf(hif(acc[1]));
            float gA = fmaxf(lof(acc[2]), 0.f), gB = fmaxf(hif(acc[2]), 0.f);
            float oA = sigf(lof(acc[3])), oB = sigf(hif(acc[3]));

            cA = fA * cA + iA * gA;
            cB = fB * cB + iB * gB;
            float hA = oA * fmaxf(cA, 0.f);
            float hB = oB * fmaxf(cB, 0.f);

            __syncwarp();
            h2[w][p][jj] = __hiloint2double(__float_as_int(hB), __float_as_int(hA));
            __syncwarp();
        }
    }

    // dense: out = normalize(sigmoid(h @ Wd + bd))
    ull acc[4];
#pragma unroll
    for (int m = 0; m < 4; m++) acc[m] = d2u(bdd[jj + 16 * m]);
    const double* wb = Wd2d + jj;
#pragma unroll
    for (int k = 0; k < 16; k++) {
        ull hv = d2u(hrow[k]);
        const double* wp = wb + k * 64;
        acc[0] = fma2(hv, d2u(wp[0]),  acc[0]);
        acc[1] = fma2(hv, d2u(wp[16]), acc[1]);
        acc[2] = fma2(hv, d2u(wp[32]), acc[2]);
        acc[3] = fma2(hv, d2u(wp[48]), acc[3]);
    }
    float sA[4], sB[4], sumA = 0.f, sumB = 0.f;
#pragma unroll
    for (int m = 0; m < 4; m++) {
        sA[m] = sigf(lof(acc[m]));  sB[m] = sigf(hif(acc[m]));
        sumA += sA[m];  sumB += sB[m];
    }
#pragma unroll
    for (int off = 1; off < 16; off <<= 1) {
        sumA += __shfl_xor_sync(0xffffffffu, sumA, off);
        sumB += __shfl_xor_sync(0xffffffffu, sumB, off);
    }
    const float invA = __fdividef(1.f, sumA);
    const float invB = __fdividef(1.f, sumB);
    float* oA = out + (size_t)(2 * P) * 64;
    float* oB = oA + 64;
#pragma unroll
    for (int m = 0; m < 4; m++) {
        oA[jj + 16 * m] = sA[m] * invA;
        oB[jj + 16 * m] = sB[m] * invB;
    }
}

extern "C" void kernel_launch(void* const* d_in, const int* in_sizes, int n_in,
                              void* d_out, int out_size)
{
    const float* x  = (const float*)d_in[0];
    const float* W  = (const float*)d_in[1];
    const float* U  = (const float*)d_in[2];
    const float* b  = (const float*)d_in[3];
    const float* Wd = (const float*)d_in[4];
    const float* bd = (const float*)d_in[5];
    float* out = (float*)d_out;

    const size_t sh1 = (2176 + 64 * 65) * sizeof(double);   // 50688 B
    cudaFuncSetAttribute(p1_kernel, cudaFuncAttributeMaxDynamicSharedMemorySize, (int)sh1);
    p1_kernel<<<4096, 128, sh1>>>(x, W, b);
    p2_kernel<<<256, 128>>>(U, Wd, bd, out);
}